// round 14
// baseline (speedup 1.0000x reference)
#include <cuda_runtime.h>
#include <cstdint>

#define TT  64
#define BB  128
#define NS  64
#define NC  32
#define NSC 96
#define NTH 640
#define FULLMASK 0xffffffffu

#define SV_STRIDE 68   // 64 + 4 pad
#define SW_STRIDE 100  // 96 + 4 pad
#define SK_STRIDE 68

typedef unsigned long long u64;

__device__ float g_K[TT * BB * NC * NS];   // [t][b][m][i]
__device__ float g_k[TT * BB * NC];        // [t][b][m]

__device__ __forceinline__ void cp16(float4* s, const float4* g) {
    uint32_t sa = (uint32_t)__cvta_generic_to_shared(s);
    asm volatile("cp.async.cg.shared.global [%0], [%1], 16;" :: "r"(sa), "l"(g));
}
__device__ __forceinline__ void cp_commit() {
    asm volatile("cp.async.commit_group;");
}
__device__ __forceinline__ void cp_wait0() {
    asm volatile("cp.async.wait_group 0;" ::: "memory");
}

__device__ __forceinline__ u64 f2dup(float a) {
    u64 d; asm("mov.b64 %0, {%1, %1};" : "=l"(d) : "f"(a)); return d;
}
__device__ __forceinline__ u64 f2pack(float lo, float hi) {
    u64 d; asm("mov.b64 %0, {%1, %2};" : "=l"(d) : "f"(lo), "f"(hi)); return d;
}
__device__ __forceinline__ void ffma2(u64& acc, u64 a, u64 b) {
    asm("fma.rn.f32x2 %0, %1, %2, %3;" : "=l"(acc) : "l"(a), "l"(b), "l"(acc));
}

// 2x4 W tile: W[i0..+1][j0..+3] = sum_k V[k][i0..] * F[k][j0..]
__device__ __forceinline__ void w_tile2(float* sW, const float* sV, const float* sF,
                                        int i0, int j0) {
    u64 acc[2][2];
    acc[0][0] = acc[0][1] = acc[1][0] = acc[1][1] = 0ull;
    #pragma unroll 4
    for (int k = 0; k < NS; k++) {
        const float2 av = *(const float2*)(sV + k * SV_STRIDE + i0);
        const ulonglong2 bv = *(const ulonglong2*)(sF + k * NSC + j0);
        const u64 d0 = f2dup(av.x);
        const u64 d1 = f2dup(av.y);
        ffma2(acc[0][0], d0, bv.x); ffma2(acc[0][1], d0, bv.y);
        ffma2(acc[1][0], d1, bv.x); ffma2(acc[1][1], d1, bv.y);
    }
    #pragma unroll
    for (int r = 0; r < 2; r++) {
        ulonglong2 o; o.x = acc[r][0]; o.y = acc[r][1];
        *(ulonglong2*)(sW + (i0 + r) * SW_STRIDE + j0) = o;
    }
}

// 2x4 Q tile (in place over C): Q += F^T W
__device__ __forceinline__ void q_tile2(float* sQ, const float* sF, const float* sW,
                                        int i0, int j0) {
    u64 acc[2][2];
    {
        const ulonglong2 c0 = *(const ulonglong2*)(sQ + i0 * NSC + j0);
        const ulonglong2 c1 = *(const ulonglong2*)(sQ + (i0 + 1) * NSC + j0);
        acc[0][0] = c0.x; acc[0][1] = c0.y; acc[1][0] = c1.x; acc[1][1] = c1.y;
    }
    #pragma unroll 4
    for (int k = 0; k < NS; k++) {
        const float2 av = *(const float2*)(sF + k * NSC + i0);
        const ulonglong2 bv = *(const ulonglong2*)(sW + k * SW_STRIDE + j0);
        const u64 d0 = f2dup(av.x);
        const u64 d1 = f2dup(av.y);
        ffma2(acc[0][0], d0, bv.x); ffma2(acc[0][1], d0, bv.y);
        ffma2(acc[1][0], d1, bv.x); ffma2(acc[1][1], d1, bv.y);
    }
    #pragma unroll
    for (int r = 0; r < 2; r++) {
        ulonglong2 o; o.x = acc[r][0]; o.y = acc[r][1];
        *(ulonglong2*)(sQ + (i0 + r) * NSC + j0) = o;
    }
}

static __global__ void __launch_bounds__(NTH, 1)
lqr_kernel(const float* __restrict__ gC, const float* __restrict__ gc,
           const float* __restrict__ gF, const float* __restrict__ gf,
           const float* __restrict__ gx0, float* __restrict__ gout)
{
    extern __shared__ float sm[];
    float* sC0   = sm;                       // 9216
    float* sC1   = sC0 + NSC * NSC;          // 9216
    float* sF0   = sC1 + NSC * NSC;          // 6144
    float* sF1   = sF0 + NS * NSC;           // 6144
    float* sV    = sF1 + NS * NSC;           // 64*68
    float* sW    = sV + NS * SV_STRIDE;      // 64*100
    float* sL    = sW + NS * SW_STRIDE;      // 32*33
    float* sLinv = sL + NC * 33;             // 32
    float* sLi   = sLinv + NC;               // 32*33
    float* sG    = sLi + NC * 33;            // 32*68
    float* sK    = sG + NC * 68;             // 32*68
    float* sc0   = sK + NC * SK_STRIDE;      // 96
    float* sc1   = sc0 + NSC;                // 96
    float* sf0   = sc1 + NSC;                // 64
    float* sf1   = sf0 + NS;                 // 64
    float* sk0   = sf1 + NS;                 // 32
    float* sk1   = sk0 + NC;                 // 32
    float* sq    = sk1 + NC;                 // 96
    float* sv    = sq + NSC;                 // 64
    float* skv   = sv + NS;                  // 32
    float* sx    = skv + NC;                 // 64
    float* stau  = sx + NS;                  // 96

    const int tid  = threadIdx.x;
    const int b    = blockIdx.x;
    const int lane = tid & 31;
    const int warp = tid >> 5;

    // ---- per-thread tile maps ----
    // P1: 768 2x4 W tiles (32x24 grid). threads 0..575 do tile tid;
    // threads 0..191 also do tile 576+tid; threads 576..639 prefetch.
    const int w1i0 = (tid / 24) * 2, w1j0 = (tid % 24) * 4;          // valid tid<576
    const int w2i0 = ((576 + tid) / 24) * 2, w2j0 = ((576 + tid) % 24) * 4; // tid<192
    // P2: lower-tri 2x4 tiles (ti 0..47, tj 0..ti>>1): 600 total.
    //   Quu subset (ti>=32 && tj>=16): 72 -> threads 0..71
    //   main subset: 528 -> threads 96..623
    int p2i0 = -1, p2j0 = 0, quui0 = -1, quuj0 = 0;
    {
        int mcnt = 0, qcnt = 0;
        for (int ti = 0; ti < 48; ti++) {
            const int cmax = ti >> 1;
            for (int tj = 0; tj <= cmax; tj++) {
                if (ti >= 32 && tj >= 16) {
                    if (qcnt == tid) { quui0 = ti * 2; quuj0 = tj * 4; }
                    qcnt++;
                } else {
                    if (mcnt == tid - 96) { p2i0 = ti * 2; p2j0 = tj * 4; }
                    mcnt++;
                }
            }
        }
    }
    // P5: 544 1x4 lower-tri V tiles -> threads 0..543; vn -> 544..607
    int p5i = -1, p5j0 = 0;
    {
        int cnt = 0;
        for (int i = 0; i < 64; i++) {
            const int c = (i >> 2) + 1;
            if (tid >= cnt && tid < cnt + c) { p5i = i; p5j0 = (tid - cnt) * 4; }
            cnt += c;
        }
        if (tid >= 544) p5i = -1;
    }

    // ---- pre-issue loads for t = TT-1 (parity 1), all threads ----
    {
        const long base = (long)((TT - 1) * BB + b);
        const float4* Cg = (const float4*)(gC + base * (long)(NSC * NSC));
        const float4* Fg = (const float4*)(gF + base * (long)(NS * NSC));
        const float4* cg = (const float4*)(gc + base * NSC);
        const float4* fg = (const float4*)(gf + base * NS);
        for (int i = tid; i < (NSC * NSC) / 4; i += NTH) cp16((float4*)sC1 + i, Cg + i);
        for (int i = tid; i < (NS * NSC) / 4; i += NTH)  cp16((float4*)sF1 + i, Fg + i);
        if (tid < NSC / 4) cp16((float4*)sc1 + tid, cg + tid);
        if (tid < NS / 4)  cp16((float4*)sf1 + tid, fg + tid);
        cp_commit();
    }

    // V = 0, v = 0
    for (int i = tid; i < NS * SV_STRIDE; i += NTH) sV[i] = 0.0f;
    if (tid < NS) sv[tid] = 0.0f;

    // ================= Backward Riccati pass =================
    for (int t = TT - 1; t >= 0; --t) {
        const long base = (long)(t * BB + b);
        float* sQ  = (t & 1) ? sC1 : sC0;
        float* sF  = (t & 1) ? sF1 : sF0;
        float* scv = (t & 1) ? sc1 : sc0;
        float* sfv = (t & 1) ? sf1 : sf0;

        cp_wait0();
        __syncthreads();                     // S1

        // ---- P1: W = V @ F (768 2x4 tiles) + prefetch on warps 18-19 ----
        if (tid < 576) {
            w_tile2(sW, sV, sF, w1i0, w1j0);
            if (tid < 192) w_tile2(sW, sV, sF, w2i0, w2j0);
        } else {
            if (t > 0) {
                const long nb = base - BB;
                float* Cn = (t & 1) ? sC0 : sC1;
                float* Fn = (t & 1) ? sF0 : sF1;
                float* cn = (t & 1) ? sc0 : sc1;
                float* fn = (t & 1) ? sf0 : sf1;
                const float4* Cg = (const float4*)(gC + nb * (long)(NSC * NSC));
                const float4* Fg = (const float4*)(gF + nb * (long)(NS * NSC));
                const float4* cg = (const float4*)(gc + nb * NSC);
                const float4* fg = (const float4*)(gf + nb * NS);
                const int tp = tid - 576;
                for (int i = tp; i < (NSC * NSC) / 4; i += 64) cp16((float4*)Cn + i, Cg + i);
                for (int i = tp; i < (NS * NSC) / 4; i += 64)  cp16((float4*)Fn + i, Fg + i);
                if (tp < NSC / 4) cp16((float4*)cn + tp, cg + tp);
                if (tp < NS / 4)  cp16((float4*)fn + tp, fg + tp);
                cp_commit();
            } else {
                cp_commit();
            }
        }
        __syncthreads();                     // S2

        // ---- P2: Q(lower) = C + F^T W ; q = c + F^T v + W^T f ;
        //      Cholesky on warp 0 overlapped ----
        if (tid < 96) {
            if (tid < 72) q_tile2(sQ, sF, sW, quui0, quuj0);   // Quu 72 tiles
            asm volatile("bar.sync 1, 96;" ::: "memory");
            if (warp == 0) {
                // Cholesky of Quu in registers (shfl)
                float a[NC];
                #pragma unroll
                for (int p = 0; p < NC; p++)
                    a[p] = (p <= lane) ? sQ[(NS + lane) * NSC + NS + p] : 0.0f;
                #pragma unroll
                for (int j = 0; j < NC; j++) {
                    const float dj = __shfl_sync(FULLMASK, a[j], j);
                    const float rinv = rsqrtf(dj);
                    const float lij = a[j] * rinv;
                    if (lane >= j) sL[lane * 33 + j] = lij;
                    if (lane == j) sLinv[j] = rinv;
                    #pragma unroll
                    for (int p = j + 1; p < NC; p++) {
                        const float v = __shfl_sync(FULLMASK, lij, p);
                        if (p <= lane) a[p] -= lij * v;
                    }
                }
                // Triangular inverse: lane j computes column j of Linv
                float x[NC];
                #pragma unroll
                for (int i = 0; i < NC; i++) x[i] = 0.0f;
                #pragma unroll
                for (int i = 0; i < NC; i++) {
                    float s0 = 0.f, s1 = 0.f, s2 = 0.f, s3 = 0.f;
                    #pragma unroll
                    for (int p = 0; p < i; p++) {
                        const float tv = sL[i * 33 + p] * x[p];
                        if ((p & 3) == 0)      s0 += tv;
                        else if ((p & 3) == 1) s1 += tv;
                        else if ((p & 3) == 2) s2 += tv;
                        else                   s3 += tv;
                    }
                    const float s = (s0 + s1) + (s2 + s3);
                    const float val = (i == lane) ? sLinv[i] : (-sLinv[i] * s);
                    x[i] = (i >= lane) ? val : 0.0f;
                }
                #pragma unroll
                for (int i = 0; i < NC; i++)
                    if (i >= lane) sLi[i * 33 + lane] = x[i];
            } else {
                // threads 32-95: q entries (e = tid-32, and e+64 for tid<64)
                const int e = tid - 32;
                {
                    float a = scv[e];
                    #pragma unroll 4
                    for (int s = 0; s < NS; s++) a += sF[s * NSC + e] * sv[s];
                    #pragma unroll 4
                    for (int s = 0; s < NS; s++) a += sW[s * SW_STRIDE + e] * sfv[s];
                    sq[e] = a;
                }
                if (tid < 64) {
                    const int j = e + 64;
                    float a = scv[j];
                    #pragma unroll 4
                    for (int s = 0; s < NS; s++) a += sF[s * NSC + j] * sv[s];
                    #pragma unroll 4
                    for (int s = 0; s < NS; s++) a += sW[s * SW_STRIDE + j] * sfv[s];
                    sq[j] = a;
                }
            }
        } else if (p2i0 >= 0) {
            q_tile2(sQ, sF, sW, p2i0, p2j0);                   // 528 main tiles
        }
        __syncthreads();                     // S3

        // ---- P4a: G = -Linv @ [Qux | qu] ----
        if (tid < 512) {
            const int i = tid >> 4, c0 = (tid & 15) << 2;
            float a0 = 0.f, a1 = 0.f, a2 = 0.f, a3 = 0.f;
            #pragma unroll 4
            for (int p = 0; p <= i; p++) {
                const float li = sLi[i * 33 + p];
                const float4 r = *(const float4*)(sQ + (NS + p) * NSC + c0);
                a0 -= li * r.x; a1 -= li * r.y; a2 -= li * r.z; a3 -= li * r.w;
            }
            *(float4*)(sG + i * 68 + c0) = make_float4(a0, a1, a2, a3);
            if (tid < NC) {
                const int ii = tid; float a = 0.f;
                for (int p = 0; p <= ii; p++) a -= sLi[ii * 33 + p] * sq[NS + p];
                sG[ii * 68 + 64] = a;
            }
        }
        __syncthreads();                     // S4

        // ---- P4b: K = Linv^T @ G ; write to smem + gmem ----
        if (tid < 512) {
            const int m = tid >> 4, c0 = (tid & 15) << 2;
            float a0 = 0.f, a1 = 0.f, a2 = 0.f, a3 = 0.f;
            #pragma unroll 4
            for (int i = m; i < NC; i++) {
                const float li = sLi[i * 33 + m];
                const float4 g4 = *(const float4*)(sG + i * 68 + c0);
                a0 += li * g4.x; a1 += li * g4.y; a2 += li * g4.z; a3 += li * g4.w;
            }
            const float4 kk = make_float4(a0, a1, a2, a3);
            *(float4*)(sK + m * SK_STRIDE + c0) = kk;
            *(float4*)(g_K + base * (long)(NC * NS) + m * NS + c0) = kk;
            if (tid < NC) {
                const int mm = tid; float a = 0.f;
                for (int i = mm; i < NC; i++) a += sLi[i * 33 + mm] * sG[i * 68 + 64];
                skv[mm] = a;
                g_k[base * NC + mm] = a;
            }
        }
        __syncthreads();                     // S5

        // ---- P5: V lower = Qxx + Qxu@K, mirrored ; vn = qx + Qxu k ----
        if (p5i >= 0) {
            const int i = p5i, j0 = p5j0;
            float a[4];
            #pragma unroll
            for (int cc = 0; cc < 4; cc++) {
                const int j = j0 + cc;
                a[cc] = (j <= i) ? sQ[i * NSC + j] : sQ[j * NSC + i];
            }
            #pragma unroll 4
            for (int m = 0; m < NC; m++) {
                const float qa = sQ[(NS + m) * NSC + i];
                const float4 kb = *(const float4*)(sK + m * SK_STRIDE + j0);
                a[0] += qa * kb.x; a[1] += qa * kb.y;
                a[2] += qa * kb.z; a[3] += qa * kb.w;
            }
            #pragma unroll
            for (int cc = 0; cc < 4; cc++) {
                const int j = j0 + cc;
                if (j <= i) {
                    sV[i * SV_STRIDE + j] = a[cc];
                    sV[j * SV_STRIDE + i] = a[cc];
                }
            }
        } else if (tid >= 544 && tid < 608) {
            const int i = tid - 544;
            float a = sq[i];
            #pragma unroll 4
            for (int m = 0; m < NC; m++) a += sQ[(NS + m) * NSC + i] * skv[m];
            sv[i] = a;
        }
        // next iteration's S1 covers sV/sv visibility
    }

    __syncthreads();   // protect sC0/sF0 reuse before forward prefetch

    // ================= Forward rollout (double-buffered) =================
    if (tid < NS) sx[tid] = gx0[b * NS + tid];
    {
        const long base = (long)b;
        const float4* Fg = (const float4*)(gF + base * (long)(NS * NSC));
        const float4* Kg = (const float4*)(g_K + base * (long)(NC * NS));
        const float4* fg = (const float4*)(gf + base * NS);
        const float4* kg = (const float4*)(g_k + base * NC);
        for (int i = tid; i < (NS * NSC) / 4; i += NTH) cp16((float4*)sF0 + i, Fg + i);
        for (int i = tid; i < (NC * NS) / 4; i += NTH)  cp16((float4*)sC0 + i, Kg + i);
        if (tid < NS / 4) cp16((float4*)sf0 + tid, fg + tid);
        if (tid < NC / 4) cp16((float4*)sk0 + tid, kg + tid);
        cp_commit();
    }
    __syncthreads();

    for (int t = 0; t < TT; t++) {
        const long base = (long)(t * BB + b);
        float* sFc = (t & 1) ? sF1 : sF0;
        float* sKc = (t & 1) ? sC1 : sC0;   // K stored [m][i], stride NS
        float* sfc = (t & 1) ? sf1 : sf0;
        float* skc = (t & 1) ? sk1 : sk0;

        cp_wait0();
        __syncthreads();

        if (t + 1 < TT) {
            const long nb = base + BB;
            float* Fn = (t & 1) ? sF0 : sF1;
            float* Kn = (t & 1) ? sC0 : sC1;
            float* fn = (t & 1) ? sf0 : sf1;
            float* kn = (t & 1) ? sk0 : sk1;
            const float4* Fg = (const float4*)(gF + nb * (long)(NS * NSC));
            const float4* Kg = (const float4*)(g_K + nb * (long)(NC * NS));
            const float4* fg = (const float4*)(gf + nb * NS);
            const float4* kg = (const float4*)(g_k + nb * NC);
            for (int i = tid; i < (NS * NSC) / 4; i += NTH) cp16((float4*)Fn + i, Fg + i);
            for (int i = tid; i < (NC * NS) / 4; i += NTH)  cp16((float4*)Kn + i, Kg + i);
            if (tid < NS / 4) cp16((float4*)fn + tid, fg + tid);
            if (tid < NC / 4) cp16((float4*)kn + tid, kg + tid);
            cp_commit();
        }

        // u[m] = K[m,:] x + k[m]  (2 rows per warp, warps 0-15)
        if (warp < 16) {
            #pragma unroll
            for (int mm = 0; mm < 2; mm++) {
                const int m = warp * 2 + mm;
                float p = sKc[m * NS + lane] * sx[lane]
                        + sKc[m * NS + 32 + lane] * sx[32 + lane];
                #pragma unroll
                for (int off = 16; off > 0; off >>= 1)
                    p += __shfl_xor_sync(FULLMASK, p, off);
                if (lane == 0) stau[NS + m] = p + skc[m];
            }
        }
        if (tid < NS) stau[tid] = sx[tid];
        __syncthreads();

        // write tau ; x_next = F tau + f  (4 rows per warp, warps 0-15)
        if (tid < NSC) gout[base * NSC + tid] = stau[tid];
        if (warp < 16) {
            #pragma unroll
            for (int ss = 0; ss < 4; ss++) {
                const int s = warp * 4 + ss;
                float p = 0.0f;
                #pragma unroll
                for (int q = 0; q < 3; q++)
                    p += sFc[s * NSC + lane + 32 * q] * stau[lane + 32 * q];
                #pragma unroll
                for (int off = 16; off > 0; off >>= 1)
                    p += __shfl_xor_sync(FULLMASK, p, off);
                if (lane == 0) sx[s] = p + sfc[s];
            }
        }
        __syncthreads();
    }
}

extern "C" void kernel_launch(void* const* d_in, const int* in_sizes, int n_in,
                              void* d_out, int out_size)
{
    const float* gC  = (const float*)d_in[0];
    const float* gc  = (const float*)d_in[1];
    const float* gF  = (const float*)d_in[2];
    const float* gf  = (const float*)d_in[3];
    const float* gx0 = (const float*)d_in[4];
    float* gout = (float*)d_out;

    const int smem_floats =
        2 * NSC * NSC + 2 * NS * NSC + NS * SV_STRIDE + NS * SW_STRIDE +
        NC * 33 + NC + NC * 33 + NC * 68 + NC * SK_STRIDE +
        2 * NSC + 2 * NS + 2 * NC + NSC + NS + NC + NS + NSC;
    const int smem_bytes = smem_floats * (int)sizeof(float);

    cudaFuncSetAttribute(lqr_kernel,
                         cudaFuncAttributeMaxDynamicSharedMemorySize, smem_bytes);
    lqr_kernel<<<BB, NTH, smem_bytes>>>(gC, gc, gF, gf, gx0, gout);
}

// round 15
// speedup vs baseline: 1.1739x; 1.1739x over previous
#include <cuda_runtime.h>
#include <cstdint>

#define TT  64
#define BB  128
#define NS  64
#define NC  32
#define NSC 96
#define NTH 512
#define FULLMASK 0xffffffffu

#define SV_STRIDE 68   // 64 + 4 pad
#define SW_STRIDE 100  // 96 + 4 pad
#define SK_STRIDE 68

typedef unsigned long long u64;

// Gains produced by backward pass, consumed by forward rollout.
__device__ float g_K[TT * BB * NC * NS];   // [t][b][m][i]
__device__ float g_k[TT * BB * NC];        // [t][b][m]

__device__ __forceinline__ void cp16(float4* s, const float4* g) {
    uint32_t sa = (uint32_t)__cvta_generic_to_shared(s);
    asm volatile("cp.async.cg.shared.global [%0], [%1], 16;" :: "r"(sa), "l"(g));
}
__device__ __forceinline__ void cp_commit() {
    asm volatile("cp.async.commit_group;");
}
__device__ __forceinline__ void cp_wait0() {
    asm volatile("cp.async.wait_group 0;" ::: "memory");
}

// ---- packed f32x2 helpers (FFMA2 path, sm_100+) ----
__device__ __forceinline__ u64 f2dup(float a) {
    u64 d; asm("mov.b64 %0, {%1, %1};" : "=l"(d) : "f"(a)); return d;
}
__device__ __forceinline__ u64 f2pack(float lo, float hi) {
    u64 d; asm("mov.b64 %0, {%1, %2};" : "=l"(d) : "f"(lo), "f"(hi)); return d;
}
__device__ __forceinline__ void ffma2(u64& acc, u64 a, u64 b) {
    asm("fma.rn.f32x2 %0, %1, %2, %3;" : "=l"(acc) : "l"(a), "l"(b), "l"(acc));
}

__device__ __forceinline__ void tri_decode(int q, int& ti, int& tj) {
    int t = 0, r = q;
    while (r > t) { r -= t + 1; t++; }
    ti = t; tj = r;
}

// W tile: W[i0..+3][j0..+3] = sum_k V[k][i0..] * F[k][j0..]   (FFMA2, compact)
__device__ __forceinline__ void w_tile(float* sW, const float* sV, const float* sF,
                                       int i0, int j0) {
    u64 acc[4][2];
    #pragma unroll
    for (int r = 0; r < 4; r++) { acc[r][0] = 0ull; acc[r][1] = 0ull; }
    #pragma unroll 2
    for (int k = 0; k < NS; k++) {
        const float4 av = *(const float4*)(sV + k * SV_STRIDE + i0);
        const ulonglong2 bv = *(const ulonglong2*)(sF + k * NSC + j0);
        const float aa[4] = {av.x, av.y, av.z, av.w};
        #pragma unroll
        for (int r = 0; r < 4; r++) {
            const u64 ad = f2dup(aa[r]);
            ffma2(acc[r][0], ad, bv.x);
            ffma2(acc[r][1], ad, bv.y);
        }
    }
    #pragma unroll
    for (int r = 0; r < 4; r++) {
        ulonglong2 o; o.x = acc[r][0]; o.y = acc[r][1];
        *(ulonglong2*)(sW + (i0 + r) * SW_STRIDE + j0) = o;
    }
}

// Q tile: Q[i0..+3][j0..+3] = C(in place) + sum_k F[k][i0..]*W[k][j0..]  (FFMA2)
__device__ __forceinline__ void q_tile(float* sQ, const float* sF, const float* sW,
                                       int i0, int j0) {
    u64 acc[4][2];
    #pragma unroll
    for (int r = 0; r < 4; r++) {
        const ulonglong2 c2 = *(const ulonglong2*)(sQ + (i0 + r) * NSC + j0);
        acc[r][0] = c2.x; acc[r][1] = c2.y;
    }
    #pragma unroll 2
    for (int k = 0; k < NS; k++) {
        const float4 av = *(const float4*)(sF + k * NSC + i0);
        const ulonglong2 bv = *(const ulonglong2*)(sW + k * SW_STRIDE + j0);
        const float aa[4] = {av.x, av.y, av.z, av.w};
        #pragma unroll
        for (int r = 0; r < 4; r++) {
            const u64 ad = f2dup(aa[r]);
            ffma2(acc[r][0], ad, bv.x);
            ffma2(acc[r][1], ad, bv.y);
        }
    }
    #pragma unroll
    for (int r = 0; r < 4; r++) {
        ulonglong2 o; o.x = acc[r][0]; o.y = acc[r][1];
        *(ulonglong2*)(sQ + (i0 + r) * NSC + j0) = o;
    }
}

static __global__ void __launch_bounds__(NTH, 1)
lqr_kernel(const float* __restrict__ gC, const float* __restrict__ gc,
           const float* __restrict__ gF, const float* __restrict__ gf,
           const float* __restrict__ gx0, float* __restrict__ gout)
{
    extern __shared__ float sm[];
    float* sC0   = sm;                       // 9216 (C/Q buf parity0; K buf in rollout)
    float* sC1   = sC0 + NSC * NSC;          // 9216
    float* sF0   = sC1 + NSC * NSC;          // 6144
    float* sF1   = sF0 + NS * NSC;           // 6144
    float* sV    = sF1 + NS * NSC;           // 64*68
    float* sW    = sV + NS * SV_STRIDE;      // 64*100
    float* sL    = sW + NS * SW_STRIDE;      // 32*33
    float* sLinv = sL + NC * 33;             // 32
    float* sLi   = sLinv + NC;               // 32*33 (triangular inverse)
    float* sG    = sLi + NC * 33;            // 32*68
    float* sK    = sG + NC * 68;             // 32*68
    float* sc0   = sK + NC * SK_STRIDE;      // 96
    float* sc1   = sc0 + NSC;                // 96
    float* sf0   = sc1 + NSC;                // 64
    float* sf1   = sf0 + NS;                 // 64
    float* sk0   = sf1 + NS;                 // 32
    float* sk1   = sk0 + NC;                 // 32
    float* sq    = sk1 + NC;                 // 96
    float* sv    = sq + NSC;                 // 64
    float* sh    = sv + NS;                  // 64
    float* skv   = sh + NS;                  // 32
    float* sx    = skv + NC;                 // 64
    float* stau  = sx + NS;                  // 96

    const int tid  = threadIdx.x;
    const int b    = blockIdx.x;
    const int lane = tid & 31;
    const int warp = tid >> 5;

    // ---- per-thread tile maps (constant over t) ----
    // P1 W_u: tid 0..127 -> 16x8 tiles over j in [64,96)
    const int wui0 = (tid >> 3) * 4;
    const int wuj0 = 64 + (tid & 7) * 4;
    // P1 W_x: tid 128..383 -> 16x16 tiles over j in [0,64)
    const int wxg  = tid - 128;
    const int wxi0 = (wxg >> 4) * 4;
    const int wxj0 = (wxg & 15) * 4;
    // P2 main set (threads 32..295): 128 Qxu tiles + 136 Qxx lower tiles
    int p2i0 = -1, p2j0 = 0;
    if (tid >= 32 && tid < 296) {
        const int g = tid - 32;
        int ti, tj;
        if (g < 128) { ti = 16 + (g >> 4); tj = g & 15; }
        else          tri_decode(g - 128, ti, tj);
        p2i0 = ti * 4; p2j0 = tj * 4;
    }
    // P2 Quu set (threads 32..67): 36 lower tiles of Quu
    int quui0 = -1, quuj0 = 0;
    if (tid >= 32 && tid < 68) {
        int ti, tj; tri_decode(tid - 32, ti, tj);
        quui0 = (16 + ti) * 4; quuj0 = (16 + tj) * 4;
    }
    // P5: lower-triangle V tiles, 2 rows x 4 cols, 272 tiles
    int p5i0 = -1, p5j0 = 0;
    {
        int r = tid;
        for (int ti = 0; ti < 32; ti++) {
            const int c = (ti >> 1) + 1;
            if (r < c) { p5i0 = ti * 2; p5j0 = r * 4; break; }
            r -= c;
        }
        if (tid >= 272) p5i0 = -1;
    }

    // ---- pre-issue loads for t = TT-1 (buffer parity 1), all threads ----
    {
        const long base = (long)((TT - 1) * BB + b);
        const float4* Cg = (const float4*)(gC + base * (long)(NSC * NSC));
        const float4* Fg = (const float4*)(gF + base * (long)(NS * NSC));
        const float4* cg = (const float4*)(gc + base * NSC);
        const float4* fg = (const float4*)(gf + base * NS);
        for (int i = tid; i < (NSC * NSC) / 4; i += NTH) cp16((float4*)sC1 + i, Cg + i);
        for (int i = tid; i < (NS * NSC) / 4; i += NTH)  cp16((float4*)sF1 + i, Fg + i);
        if (tid < NSC / 4) cp16((float4*)sc1 + tid, cg + tid);
        if (tid < NS / 4)  cp16((float4*)sf1 + tid, fg + tid);
        cp_commit();
    }

    // V = 0, v = 0
    for (int i = tid; i < NS * SV_STRIDE; i += NTH) sV[i] = 0.0f;
    if (tid < NS) sv[tid] = 0.0f;

    // ================= Backward Riccati pass =================
    for (int t = TT - 1; t >= 0; --t) {
        const long base = (long)(t * BB + b);
        float* sQ  = (t & 1) ? sC1 : sC0;
        float* sF  = (t & 1) ? sF1 : sF0;
        float* scv = (t & 1) ? sc1 : sc0;
        float* sfv = (t & 1) ? sf1 : sf0;

        cp_wait0();
        __syncthreads();                     // S1

        // ---- P1/P2 pipelined via named barriers ----
        if (tid < 128) {
            // warps 0-3: W u-columns first, then Quu -> Cholesky path
            w_tile(sW, sV, sF, wui0, wuj0);
            asm volatile("bar.sync 1, 128;" ::: "memory");
            if (quui0 >= 0) q_tile(sQ, sF, sW, quui0, quuj0);   // tid 32..67
            if (warp < 3) asm volatile("bar.sync 2, 96;" ::: "memory");
            if (warp == 0) {
                // Cholesky of Quu in registers (shfl)
                float a[NC];
                #pragma unroll
                for (int p = 0; p < NC; p++)
                    a[p] = (p <= lane) ? sQ[(NS + lane) * NSC + NS + p] : 0.0f;
                #pragma unroll
                for (int j = 0; j < NC; j++) {
                    const float dj = __shfl_sync(FULLMASK, a[j], j);
                    const float rinv = rsqrtf(dj);
                    const float lij = a[j] * rinv;
                    if (lane >= j) sL[lane * 33 + j] = lij;
                    if (lane == j) sLinv[j] = rinv;
                    #pragma unroll
                    for (int p = j + 1; p < NC; p++) {
                        const float v = __shfl_sync(FULLMASK, lij, p);
                        if (p <= lane) a[p] -= lij * v;
                    }
                }
                // Triangular inverse: lane j computes column j of Linv
                float x[NC];
                #pragma unroll
                for (int i = 0; i < NC; i++) x[i] = 0.0f;
                #pragma unroll
                for (int i = 0; i < NC; i++) {
                    float s0 = 0.f, s1 = 0.f, s2 = 0.f, s3 = 0.f;
                    #pragma unroll
                    for (int p = 0; p < i; p++) {
                        const float tv = sL[i * 33 + p] * x[p];
                        if ((p & 3) == 0)      s0 += tv;
                        else if ((p & 3) == 1) s1 += tv;
                        else if ((p & 3) == 2) s2 += tv;
                        else                   s3 += tv;
                    }
                    const float s = (s0 + s1) + (s2 + s3);
                    const float val = (i == lane) ? sLinv[i] : (-sLinv[i] * s);
                    x[i] = (i >= lane) ? val : 0.0f;
                }
                #pragma unroll
                for (int i = 0; i < NC; i++)
                    if (i >= lane) sLi[i * 33 + lane] = x[i];
            } else {
                asm volatile("bar.sync 4, 480;" ::: "memory");   // warps 1-3
                if (p2i0 >= 0) q_tile(sQ, sF, sW, p2i0, p2j0);   // tid 32..127
            }
        } else {
            // warps 4-15: W x-columns / h / prefetch / q, then main Q tiles
            if (tid < 384) {
                w_tile(sW, sV, sF, wxi0, wxj0);
            } else {
                if (tid < 448) {
                    // warps 12-13: h = v + V f   (64 entries, V symmetric)
                    const int s = tid - 384;
                    float a = sv[s];
                    #pragma unroll 4
                    for (int p = 0; p < NS; p++) a += sV[p * SV_STRIDE + s] * sfv[p];
                    sh[s] = a;
                } else {
                    // warps 14-15: prefetch step t-1 into the other buffers
                    if (t > 0) {
                        const long nb = base - BB;
                        float* Cn = (t & 1) ? sC0 : sC1;
                        float* Fn = (t & 1) ? sF0 : sF1;
                        float* cn = (t & 1) ? sc0 : sc1;
                        float* fn = (t & 1) ? sf0 : sf1;
                        const float4* Cg = (const float4*)(gC + nb * (long)(NSC * NSC));
                        const float4* Fg = (const float4*)(gF + nb * (long)(NS * NSC));
                        const float4* cg = (const float4*)(gc + nb * NSC);
                        const float4* fg = (const float4*)(gf + nb * NS);
                        const int tp = tid - 448;
                        for (int i = tp; i < (NSC * NSC) / 4; i += 64) cp16((float4*)Cn + i, Cg + i);
                        for (int i = tp; i < (NS * NSC) / 4; i += 64)  cp16((float4*)Fn + i, Fg + i);
                        if (tp < NSC / 4) cp16((float4*)cn + tp, cg + tp);
                        if (tp < NS / 4)  cp16((float4*)fn + tp, fg + tp);
                        cp_commit();
                    } else {
                        cp_commit();   // keep wait_group semantics uniform
                    }
                }
                // h ready -> q = c + F^T h  (96 entries on threads 384..479)
                asm volatile("bar.sync 5, 128;" ::: "memory");   // warps 12-15
                if (tid < 480) {
                    const int j = tid - 384;
                    float a = scv[j];
                    #pragma unroll 4
                    for (int s = 0; s < NS; s++) a += sF[s * NSC + j] * sh[s];
                    sq[j] = a;
                }
            }
            asm volatile("bar.sync 4, 480;" ::: "memory");
            if (p2i0 >= 0) q_tile(sQ, sF, sW, p2i0, p2j0);      // tid 128..295
        }
        __syncthreads();                     // S3

        // ---- P4a: G = -Linv @ [Qux | qu]  (parallel GEMM) ----
        {
            const int i = tid >> 4, c0 = (tid & 15) << 2;
            float a0 = 0.f, a1 = 0.f, a2 = 0.f, a3 = 0.f;
            #pragma unroll 4
            for (int p = 0; p <= i; p++) {
                const float li = sLi[i * 33 + p];
                const float4 r = *(const float4*)(sQ + (NS + p) * NSC + c0);
                a0 -= li * r.x; a1 -= li * r.y; a2 -= li * r.z; a3 -= li * r.w;
            }
            *(float4*)(sG + i * 68 + c0) = make_float4(a0, a1, a2, a3);
            if (tid < NC) {
                const int ii = tid; float a = 0.f;
                for (int p = 0; p <= ii; p++) a -= sLi[ii * 33 + p] * sq[NS + p];
                sG[ii * 68 + 64] = a;
            }
        }
        __syncthreads();                     // S4

        // ---- P4b: K = Linv^T @ G ; write K/k to smem + gmem ----
        {
            const int m = tid >> 4, c0 = (tid & 15) << 2;
            float a0 = 0.f, a1 = 0.f, a2 = 0.f, a3 = 0.f;
            #pragma unroll 4
            for (int i = m; i < NC; i++) {
                const float li = sLi[i * 33 + m];
                const float4 g4 = *(const float4*)(sG + i * 68 + c0);
                a0 += li * g4.x; a1 += li * g4.y; a2 += li * g4.z; a3 += li * g4.w;
            }
            const float4 kk = make_float4(a0, a1, a2, a3);
            *(float4*)(sK + m * SK_STRIDE + c0) = kk;
            *(float4*)(g_K + base * (long)(NC * NS) + m * NS + c0) = kk;
            if (tid < NC) {
                const int mm = tid; float a = 0.f;
                for (int i = mm; i < NC; i++) a += sLi[i * 33 + mm] * sG[i * 68 + 64];
                skv[mm] = a;
                g_k[base * NC + mm] = a;
            }
        }
        __syncthreads();                     // S5

        // ---- P5 (FFMA2): V lower = Qxx + Qxu@K, mirrored ; vn = qx + Qxu k ----
        if (p5i0 >= 0) {
            const int i0 = p5i0, j0 = p5j0;
            u64 acc[2][2];
            #pragma unroll
            for (int r = 0; r < 2; r++) {
                float e[4];
                #pragma unroll
                for (int cc = 0; cc < 4; cc++) {
                    const int i = i0 + r, j = j0 + cc;
                    e[cc] = (j <= i) ? sQ[i * NSC + j] : 0.0f;
                }
                acc[r][0] = f2pack(e[0], e[1]);
                acc[r][1] = f2pack(e[2], e[3]);
            }
            #pragma unroll 4
            for (int m = 0; m < NC; m++) {
                const float2 qa = *(const float2*)(sQ + (NS + m) * NSC + i0);
                const ulonglong2 kb = *(const ulonglong2*)(sK + m * SK_STRIDE + j0);
                const u64 d0 = f2dup(qa.x);
                const u64 d1 = f2dup(qa.y);
                ffma2(acc[0][0], d0, kb.x); ffma2(acc[0][1], d0, kb.y);
                ffma2(acc[1][0], d1, kb.x); ffma2(acc[1][1], d1, kb.y);
            }
            #pragma unroll
            for (int r = 0; r < 2; r++) {
                float e[4];
                e[0] = __uint_as_float((uint32_t)(acc[r][0] & 0xffffffffull));
                e[1] = __uint_as_float((uint32_t)(acc[r][0] >> 32));
                e[2] = __uint_as_float((uint32_t)(acc[r][1] & 0xffffffffull));
                e[3] = __uint_as_float((uint32_t)(acc[r][1] >> 32));
                #pragma unroll
                for (int cc = 0; cc < 4; cc++) {
                    const int i = i0 + r, j = j0 + cc;
                    if (j <= i) {
                        sV[i * SV_STRIDE + j] = e[cc];
                        sV[j * SV_STRIDE + i] = e[cc];
                    }
                }
            }
        }
        if (tid >= 448) {
            const int i = tid - 448;
            float a = sq[i];
            #pragma unroll 4
            for (int m = 0; m < NC; m++) a += sQ[(NS + m) * NSC + i] * skv[m];
            sv[i] = a;
        }
        // next iteration's S1 covers sV/sv visibility
    }

    __syncthreads();   // protect sC0/sF0 reuse before forward prefetch

    // ================= Forward rollout (double-buffered) =================
    if (tid < NS) sx[tid] = gx0[b * NS + tid];
    {
        const long base = (long)b;
        const float4* Fg = (const float4*)(gF + base * (long)(NS * NSC));
        const float4* Kg = (const float4*)(g_K + base * (long)(NC * NS));
        const float4* fg = (const float4*)(gf + base * NS);
        const float4* kg = (const float4*)(g_k + base * NC);
        for (int i = tid; i < (NS * NSC) / 4; i += NTH) cp16((float4*)sF0 + i, Fg + i);
        for (int i = tid; i < (NC * NS) / 4; i += NTH)  cp16((float4*)sC0 + i, Kg + i);
        if (tid < NS / 4) cp16((float4*)sf0 + tid, fg + tid);
        if (tid < NC / 4) cp16((float4*)sk0 + tid, kg + tid);
        cp_commit();
    }
    __syncthreads();

    for (int t = 0; t < TT; t++) {
        const long base = (long)(t * BB + b);
        float* sFc = (t & 1) ? sF1 : sF0;
        float* sKc = (t & 1) ? sC1 : sC0;   // K stored [m][i], stride NS
        float* sfc = (t & 1) ? sf1 : sf0;
        float* skc = (t & 1) ? sk1 : sk0;

        cp_wait0();
        __syncthreads();

        if (t + 1 < TT) {
            const long nb = base + BB;
            float* Fn = (t & 1) ? sF0 : sF1;
            float* Kn = (t & 1) ? sC0 : sC1;
            float* fn = (t & 1) ? sf0 : sf1;
            float* kn = (t & 1) ? sk0 : sk1;
            const float4* Fg = (const float4*)(gF + nb * (long)(NS * NSC));
            const float4* Kg = (const float4*)(g_K + nb * (long)(NC * NS));
            const float4* fg = (const float4*)(gf + nb * NS);
            const float4* kg = (const float4*)(g_k + nb * NC);
            for (int i = tid; i < (NS * NSC) / 4; i += NTH) cp16((float4*)Fn + i, Fg + i);
            for (int i = tid; i < (NC * NS) / 4; i += NTH)  cp16((float4*)Kn + i, Kg + i);
            if (tid < NS / 4) cp16((float4*)fn + tid, fg + tid);
            if (tid < NC / 4) cp16((float4*)kn + tid, kg + tid);
            cp_commit();
        }

        // u[m] = K[m,:] x + k[m]  (2 rows per warp)
        #pragma unroll
        for (int mm = 0; mm < 2; mm++) {
            const int m = warp * 2 + mm;
            float p = sKc[m * NS + lane] * sx[lane]
                    + sKc[m * NS + 32 + lane] * sx[32 + lane];
            #pragma unroll
            for (int off = 16; off > 0; off >>= 1)
                p += __shfl_xor_sync(FULLMASK, p, off);
            if (lane == 0) stau[NS + m] = p + skc[m];
        }
        if (tid < NS) stau[tid] = sx[tid];
        __syncthreads();

        // write tau ; x_next = F tau + f  (4 rows per warp)
        if (tid < NSC) gout[base * NSC + tid] = stau[tid];
        #pragma unroll
        for (int ss = 0; ss < 4; ss++) {
            const int s = warp * 4 + ss;
            float p = 0.0f;
            #pragma unroll
            for (int q = 0; q < 3; q++)
                p += sFc[s * NSC + lane + 32 * q] * stau[lane + 32 * q];
            #pragma unroll
            for (int off = 16; off > 0; off >>= 1)
                p += __shfl_xor_sync(FULLMASK, p, off);
            if (lane == 0) sx[s] = p + sfc[s];
        }
        __syncthreads();
    }
}

extern "C" void kernel_launch(void* const* d_in, const int* in_sizes, int n_in,
                              void* d_out, int out_size)
{
    const float* gC  = (const float*)d_in[0];
    const float* gc  = (const float*)d_in[1];
    const float* gF  = (const float*)d_in[2];
    const float* gf  = (const float*)d_in[3];
    const float* gx0 = (const float*)d_in[4];
    float* gout = (float*)d_out;

    const int smem_floats =
        2 * NSC * NSC + 2 * NS * NSC + NS * SV_STRIDE + NS * SW_STRIDE +
        NC * 33 + NC + NC * 33 + NC * 68 + NC * SK_STRIDE +
        2 * NSC + 2 * NS + 2 * NC + NSC + NS + NS + NC + NS + NSC;
    const int smem_bytes = smem_floats * (int)sizeof(float);

    cudaFuncSetAttribute(lqr_kernel,
                         cudaFuncAttributeMaxDynamicSharedMemorySize, smem_bytes);
    lqr_kernel<<<BB, NTH, smem_bytes>>>(gC, gc, gF, gf, gx0, gout);
}